// round 2
// baseline (speedup 1.0000x reference)
#include <cuda_runtime.h>
#include <stdint.h>

#define NCONCEPTS 4096
#define CDIM      1024
#define BATCH     4096
#define KSAMP     256

// Scratch for the per-concept dot products (allocation-free rule: device global).
__device__ float g_s[NCONCEPTS];

// ---------------------------------------------------------------------------
// Kernel 1: s[c] = sum_d cb[c,d] * A[c,d]
// One warp per concept row; float4 loads; warp shuffle reduction.
// ---------------------------------------------------------------------------
__global__ __launch_bounds__(256) void rowdot_kernel(
    const float* __restrict__ cb, const float* __restrict__ attn)
{
    const int warp = threadIdx.x >> 5;
    const int lane = threadIdx.x & 31;
    const int row  = blockIdx.x * 8 + warp;

    const float4* c4 = reinterpret_cast<const float4*>(cb   + (size_t)row * CDIM);
    const float4* a4 = reinterpret_cast<const float4*>(attn + (size_t)row * CDIM);

    float sum = 0.f;
    #pragma unroll
    for (int i = 0; i < (CDIM / 4) / 32; i++) {
        float4 c = c4[lane + i * 32];
        float4 a = a4[lane + i * 32];
        sum += c.x * a.x + c.y * a.y + c.z * a.z + c.w * a.w;
    }
    #pragma unroll
    for (int o = 16; o > 0; o >>= 1)
        sum += __shfl_xor_sync(0xFFFFFFFFu, sum, o);
    if (lane == 0) g_s[row] = sum;
}

// ---------------------------------------------------------------------------
// Kernel 2: out[b, c] = (c in sampled_idx[b]) ? s[c] : 0
// One CTA per batch row. Build a 4096-bit mask in shared via atomicOr,
// cache s[] in shared, then stream the full row out as float4.
// NOTE: sampled_idx is int32 on the wire (JAX x64 disabled downgrades the
// declared int64 to int32).
// ---------------------------------------------------------------------------
__global__ __launch_bounds__(256) void scatter_kernel(
    const int* __restrict__ sampled_idx, float* __restrict__ out)
{
    __shared__ unsigned bm[NCONCEPTS / 32];   // 128 words = 512 B
    __shared__ float    s_sh[NCONCEPTS];      // 16 KB

    const int t = threadIdx.x;
    const int b = blockIdx.x;

    if (t < NCONCEPTS / 32) bm[t] = 0u;

    // Cooperative load of s[] into shared (vectorized)
    {
        float4*       d4 = reinterpret_cast<float4*>(s_sh);
        const float4* g4 = reinterpret_cast<const float4*>(g_s);
        #pragma unroll
        for (int i = 0; i < (NCONCEPTS / 4) / 256; i++)
            d4[t + i * 256] = g4[t + i * 256];
    }
    __syncthreads();

    // Each thread sets one sampled index bit (mask defensively; indices are
    // generated in [0, NCONCEPTS) so the mask is a no-op on valid data).
    {
        int ci = sampled_idx[(size_t)b * KSAMP + t] & (NCONCEPTS - 1);
        atomicOr(&bm[ci >> 5], 1u << (ci & 31));
    }
    __syncthreads();

    // Stream the row: 4096 floats = 4 chunks of 1024, float4 per thread
    float4* o4 = reinterpret_cast<float4*>(out + (size_t)b * NCONCEPTS);
    #pragma unroll
    for (int chunk = 0; chunk < 4; chunk++) {
        int c0 = chunk * 1024 + t * 4;      // 4-aligned -> all 4 bits in one word
        unsigned w = bm[c0 >> 5];
        int sh = c0 & 31;
        float4 v;
        v.x = ((w >> (sh + 0)) & 1u) ? s_sh[c0 + 0] : 0.f;
        v.y = ((w >> (sh + 1)) & 1u) ? s_sh[c0 + 1] : 0.f;
        v.z = ((w >> (sh + 2)) & 1u) ? s_sh[c0 + 2] : 0.f;
        v.w = ((w >> (sh + 3)) & 1u) ? s_sh[c0 + 3] : 0.f;
        o4[c0 >> 2] = v;
    }
}

extern "C" void kernel_launch(void* const* d_in, const int* in_sizes, int n_in,
                              void* d_out, int out_size)
{
    const float* cb   = (const float*)d_in[0];
    const float* attn = (const float*)d_in[1];
    const int*   idx  = (const int*)d_in[2];
    float*       out  = (float*)d_out;

    rowdot_kernel<<<NCONCEPTS / 8, 256>>>(cb, attn);
    scatter_kernel<<<BATCH, 256>>>(idx, out);
}

// round 3
// speedup vs baseline: 1.0274x; 1.0274x over previous
#include <cuda_runtime.h>
#include <stdint.h>

#define NCONCEPTS 4096
#define CDIM      1024
#define BATCH     4096
#define KSAMP     256
#define ROWS_PER_CTA 8

// Scratch for the per-concept dot products (allocation-free rule: device global).
__device__ float g_s[NCONCEPTS];

// ---------------------------------------------------------------------------
// Kernel 1: s[c] = sum_d cb[c,d] * A[c,d]
// One warp per concept row; float4 loads; warp shuffle reduction.
// ---------------------------------------------------------------------------
__global__ __launch_bounds__(256) void rowdot_kernel(
    const float* __restrict__ cb, const float* __restrict__ attn)
{
    const int warp = threadIdx.x >> 5;
    const int lane = threadIdx.x & 31;
    const int row  = blockIdx.x * 8 + warp;

    const float4* c4 = reinterpret_cast<const float4*>(cb   + (size_t)row * CDIM);
    const float4* a4 = reinterpret_cast<const float4*>(attn + (size_t)row * CDIM);

    float sum = 0.f;
    #pragma unroll
    for (int i = 0; i < (CDIM / 4) / 32; i++) {
        float4 c = c4[lane + i * 32];
        float4 a = a4[lane + i * 32];
        sum += c.x * a.x + c.y * a.y + c.z * a.z + c.w * a.w;
    }
    #pragma unroll
    for (int o = 16; o > 0; o >>= 1)
        sum += __shfl_xor_sync(0xFFFFFFFFu, sum, o);
    if (lane == 0) g_s[row] = sum;
}

// ---------------------------------------------------------------------------
// Kernel 2: out[b, c] = (c in sampled_idx[b]) ? s[c] : 0
// ROWS_PER_CTA batch rows per CTA. Thread t owns columns {chunk*1024 + 4t}
// for chunk=0..3 — its 16 s-values are loaded ONCE into registers. Per row:
// build 4096-bit mask in shared via atomicOr, then masked float4 stores.
// Shared usage is just the 512B mask -> L1 pipe sees only the output stores.
// ---------------------------------------------------------------------------
__global__ __launch_bounds__(256) void scatter_kernel(
    const int* __restrict__ sampled_idx, float* __restrict__ out)
{
    __shared__ unsigned bm[NCONCEPTS / 32];   // 128 words = 512 B

    const int t = threadIdx.x;

    // Load this thread's 16 s-values into registers (L2-hot, 16KB total).
    float4 sv[4];
    const float4* g4 = reinterpret_cast<const float4*>(g_s);
    #pragma unroll
    for (int c = 0; c < 4; c++)
        sv[c] = g4[c * 256 + t];

    const int row0 = blockIdx.x * ROWS_PER_CTA;

    #pragma unroll 1
    for (int r = 0; r < ROWS_PER_CTA; r++) {
        const int b = row0 + r;

        if (t < NCONCEPTS / 32) bm[t] = 0u;
        __syncthreads();                       // reset visible

        {
            int ci = sampled_idx[(size_t)b * KSAMP + t] & (NCONCEPTS - 1);
            atomicOr(&bm[ci >> 5], 1u << (ci & 31));
        }
        __syncthreads();                       // atomics visible

        float4* o4 = reinterpret_cast<float4*>(out + (size_t)b * NCONCEPTS);
        #pragma unroll
        for (int c = 0; c < 4; c++) {
            int c0 = c * 1024 + t * 4;         // word = c*32 + t/8 (broadcast read)
            unsigned w = bm[c0 >> 5];
            int sh = c0 & 31;
            float4 v;
            v.x = ((w >> (sh + 0)) & 1u) ? sv[c].x : 0.f;
            v.y = ((w >> (sh + 1)) & 1u) ? sv[c].y : 0.f;
            v.z = ((w >> (sh + 2)) & 1u) ? sv[c].z : 0.f;
            v.w = ((w >> (sh + 3)) & 1u) ? sv[c].w : 0.f;
            o4[c0 >> 2] = v;
        }
        __syncthreads();                       // mask reads done before next reset
    }
}

extern "C" void kernel_launch(void* const* d_in, const int* in_sizes, int n_in,
                              void* d_out, int out_size)
{
    const float* cb   = (const float*)d_in[0];
    const float* attn = (const float*)d_in[1];
    const int*   idx  = (const int*)d_in[2];
    float*       out  = (float*)d_out;

    rowdot_kernel<<<NCONCEPTS / 8, 256>>>(cb, attn);
    scatter_kernel<<<BATCH / ROWS_PER_CTA, 256>>>(idx, out);
}

// round 4
// speedup vs baseline: 1.1332x; 1.1030x over previous
#include <cuda_runtime.h>
#include <stdint.h>

#define NCONCEPTS 4096
#define CDIM      1024
#define BATCH     4096
#define KSAMP     256
#define ROWS_PER_CTA 4

// Scratch for the per-concept dot products (allocation-free rule: device global).
__device__ float g_s[NCONCEPTS];

// ---------------------------------------------------------------------------
// Kernel 1: s[c] = sum_d cb[c,d] * A[c,d]
// One warp per concept row; float4 loads; warp shuffle reduction.
// ---------------------------------------------------------------------------
__global__ __launch_bounds__(256) void rowdot_kernel(
    const float* __restrict__ cb, const float* __restrict__ attn)
{
    const int warp = threadIdx.x >> 5;
    const int lane = threadIdx.x & 31;
    const int row  = blockIdx.x * 8 + warp;

    const float4* c4 = reinterpret_cast<const float4*>(cb   + (size_t)row * CDIM);
    const float4* a4 = reinterpret_cast<const float4*>(attn + (size_t)row * CDIM);

    float sum = 0.f;
    #pragma unroll
    for (int i = 0; i < (CDIM / 4) / 32; i++) {
        float4 c = c4[lane + i * 32];
        float4 a = a4[lane + i * 32];
        sum += c.x * a.x + c.y * a.y + c.z * a.z + c.w * a.w;
    }
    #pragma unroll
    for (int o = 16; o > 0; o >>= 1)
        sum += __shfl_xor_sync(0xFFFFFFFFu, sum, o);
    if (lane == 0) g_s[row] = sum;
}

// ---------------------------------------------------------------------------
// Kernel 2: out[b, c] = (c in sampled_idx[b]) ? s[c] : 0
// 4 batch rows per CTA, masks for ALL rows built up front -> only 2 barriers
// per CTA, then 16 unrolled STG.128 per thread (no syncs in the store stream).
// Thread t owns columns {chunk*1024 + 4t}; its 16 s-values live in registers.
// ---------------------------------------------------------------------------
__global__ __launch_bounds__(256) void scatter_kernel(
    const int* __restrict__ sampled_idx, float* __restrict__ out)
{
    __shared__ unsigned bm[ROWS_PER_CTA][NCONCEPTS / 32];   // 4 x 512B = 2KB

    const int t = threadIdx.x;
    const int row0 = blockIdx.x * ROWS_PER_CTA;

    // This thread's 16 s-values (L2-hot read, 16KB table).
    float4 sv[4];
    const float4* g4 = reinterpret_cast<const float4*>(g_s);
    #pragma unroll
    for (int c = 0; c < 4; c++)
        sv[c] = g4[c * 256 + t];

    // Zero all masks: 512 words / 256 threads = 2 words each.
    unsigned* bmf = &bm[0][0];
    bmf[t]       = 0u;
    bmf[t + 256] = 0u;
    __syncthreads();

    // All 4 rows' indices are 1024 contiguous ints -> one int4 per thread.
    // Each int4 lies within a single row (4-aligned, 256 idx/row): row = t>>6.
    {
        const int4* i4 = reinterpret_cast<const int4*>(sampled_idx + (size_t)row0 * KSAMP);
        int4 v = i4[t];
        const int r = t >> 6;
        int a = v.x & (NCONCEPTS - 1);
        int b = v.y & (NCONCEPTS - 1);
        int c = v.z & (NCONCEPTS - 1);
        int d = v.w & (NCONCEPTS - 1);
        atomicOr(&bm[r][a >> 5], 1u << (a & 31));
        atomicOr(&bm[r][b >> 5], 1u << (b & 31));
        atomicOr(&bm[r][c >> 5], 1u << (c & 31));
        atomicOr(&bm[r][d >> 5], 1u << (d & 31));
    }
    __syncthreads();

    // Store stream: 4 rows x 4 chunks of float4 per thread, fully unrolled.
    #pragma unroll
    for (int r = 0; r < ROWS_PER_CTA; r++) {
        float4* o4 = reinterpret_cast<float4*>(out + (size_t)(row0 + r) * NCONCEPTS);
        #pragma unroll
        for (int c = 0; c < 4; c++) {
            int c0 = c * 1024 + t * 4;           // 8 threads/word -> broadcast LDS
            unsigned w = bm[r][c0 >> 5];
            int sh = c0 & 31;
            float4 v;
            v.x = ((w >> (sh + 0)) & 1u) ? sv[c].x : 0.f;
            v.y = ((w >> (sh + 1)) & 1u) ? sv[c].y : 0.f;
            v.z = ((w >> (sh + 2)) & 1u) ? sv[c].z : 0.f;
            v.w = ((w >> (sh + 3)) & 1u) ? sv[c].w : 0.f;
            o4[c0 >> 2] = v;
        }
    }
}

extern "C" void kernel_launch(void* const* d_in, const int* in_sizes, int n_in,
                              void* d_out, int out_size)
{
    const float* cb   = (const float*)d_in[0];
    const float* attn = (const float*)d_in[1];
    const int*   idx  = (const int*)d_in[2];
    float*       out  = (float*)d_out;

    rowdot_kernel<<<NCONCEPTS / 8, 256>>>(cb, attn);
    scatter_kernel<<<BATCH / ROWS_PER_CTA, 256>>>(idx, out);
}